// round 1
// baseline (speedup 1.0000x reference)
#include <cuda_runtime.h>

// Shapes (fixed by the problem)
#define Bb 256
#define Cc 256
#define CH 128
#define NN 196              // H*W = 14*14
#define N4 49               // NN / 4
#define TOT_F4 (Bb * Cc * N4)   // 3,211,264 float4 elements
#define EPS 1e-5f

// Scratch (allocation-free rule: __device__ globals)
__device__ float g_ysum[Bb * Cc];   // per-(b,c) spatial sum of y
__device__ float g_zbn[Bb * Cc];    // per-(b,o) BN-transformed bias term

// ---------------------------------------------------------------------------
// Kernel 1: ysum[b,c] = sum over 196 spatial positions of y[b,c,:,:]
// One warp per (b,c) row. Row = 49 aligned float4s.
// ---------------------------------------------------------------------------
__global__ void k_ysum(const float* __restrict__ y) {
    int warp = (blockIdx.x * blockDim.x + threadIdx.x) >> 5;
    int lane = threadIdx.x & 31;
    if (warp >= Bb * Cc) return;
    const float4* row = reinterpret_cast<const float4*>(y + (size_t)warp * NN);
    float s = 0.0f;
    // lanes 0..31 cover f4 indices {lane, lane+32} (second iter partial)
    {
        float4 v = row[lane];
        s = v.x + v.y + v.z + v.w;
    }
    int i2 = lane + 32;
    if (i2 < N4) {
        float4 v = row[i2];
        s += v.x + v.y + v.z + v.w;
    }
    #pragma unroll
    for (int o = 16; o; o >>= 1) s += __shfl_xor_sync(0xFFFFFFFFu, s, o);
    if (lane == 0) g_ysum[warp] = s;
}

// ---------------------------------------------------------------------------
// Kernel 2: per batch b:
//   tmp[ch] = sum_c Wv[ch,c] * ysum[b,c]       (softmax==1 collapse)
//   z[o]    = sum_ch Wz[o,ch] * tmp[ch]
//   zbn[o]  = (z[o]-mean[o]) * rsqrt(var[o]+eps) * w[o] + bias[o]
// One block of 256 threads per batch.
// ---------------------------------------------------------------------------
__global__ void k_proj(const float* __restrict__ Wv,
                       const float* __restrict__ Wz,
                       const float* __restrict__ bn_w,
                       const float* __restrict__ bn_b,
                       const float* __restrict__ bn_m,
                       const float* __restrict__ bn_v) {
    __shared__ float ys[Cc];
    __shared__ float tmp[CH];
    int b = blockIdx.x;
    int t = threadIdx.x;

    ys[t] = g_ysum[b * Cc + t];
    __syncthreads();

    if (t < CH) {
        const float4* wr = reinterpret_cast<const float4*>(Wv + t * Cc);
        float acc = 0.0f;
        #pragma unroll
        for (int i = 0; i < Cc / 4; i++) {
            float4 v = wr[i];
            acc += v.x * ys[4*i]   + v.y * ys[4*i+1]
                 + v.z * ys[4*i+2] + v.w * ys[4*i+3];
        }
        tmp[t] = acc;
    }
    __syncthreads();

    {
        const float4* wr = reinterpret_cast<const float4*>(Wz + t * CH);
        float acc = 0.0f;
        #pragma unroll
        for (int i = 0; i < CH / 4; i++) {
            float4 v = wr[i];
            acc += v.x * tmp[4*i]   + v.y * tmp[4*i+1]
                 + v.z * tmp[4*i+2] + v.w * tmp[4*i+3];
        }
        float inv = rsqrtf(bn_v[t] + EPS);
        g_zbn[b * Cc + t] = (acc - bn_m[t]) * inv * bn_w[t] + bn_b[t];
    }
}

// ---------------------------------------------------------------------------
// Kernel 3: out[b,c,n] = x[b,c,n] + zbn[b,c]   (fully vectorized float4)
// 196 % 4 == 0, so every float4 lies inside a single (b,c) row.
// ---------------------------------------------------------------------------
__global__ void k_out(const float* __restrict__ x, float* __restrict__ out) {
    int i = blockIdx.x * blockDim.x + threadIdx.x;   // float4 index
    if (i >= TOT_F4) return;
    int bc = i / N4;                                  // compiler -> umulhi magic
    float z = __ldg(&g_zbn[bc]);
    float4 v = reinterpret_cast<const float4*>(x)[i];
    v.x += z; v.y += z; v.z += z; v.w += z;
    reinterpret_cast<float4*>(out)[i] = v;
}

// ---------------------------------------------------------------------------
// Launch. Inputs (metadata order):
//  0:x 1:y 2:Wq 3:Wk 4:Wv 5:Wz 6:bn_weight 7:bn_bias 8:bn_mean 9:bn_var
// Wq, Wk are mathematically dead (softmax over singleton axis == 1).
// ---------------------------------------------------------------------------
extern "C" void kernel_launch(void* const* d_in, const int* in_sizes, int n_in,
                              void* d_out, int out_size) {
    const float* x    = (const float*)d_in[0];
    const float* y    = (const float*)d_in[1];
    const float* Wv   = (const float*)d_in[4];
    const float* Wz   = (const float*)d_in[5];
    const float* bn_w = (const float*)d_in[6];
    const float* bn_b = (const float*)d_in[7];
    const float* bn_m = (const float*)d_in[8];
    const float* bn_v = (const float*)d_in[9];
    float* out = (float*)d_out;

    // Kernel 1: 65536 warps, 256 threads/block -> 8192 blocks
    k_ysum<<<(Bb * Cc * 32 + 255) / 256, 256>>>(y);
    // Kernel 2: one block per batch
    k_proj<<<Bb, Cc>>>(Wv, Wz, bn_w, bn_b, bn_m, bn_v);
    // Kernel 3: one float4 per thread
    k_out<<<(TOT_F4 + 255) / 256, 256>>>(x, out);
}

// round 2
// speedup vs baseline: 1.0814x; 1.0814x over previous
#include <cuda_runtime.h>

// Shapes (fixed by the problem)
#define Bb 256
#define Cc 256
#define CH 128
#define NN 196               // H*W = 14*14
#define N4 49                // NN / 4 (float4s per channel row)
#define ROW_F4 N4
#define BATCH_F4 (Cc * N4)   // 12544 float4 per batch slab
#define THREADS 512
#define EPS 1e-5f

// ---------------------------------------------------------------------------
// Single fused kernel: one block per batch.
//   Phase 1: ys[c]  = sum_n y[b,c,n]                       (warp per channel)
//   Phase 2: tmp    = Wv @ ys ; z = Wz @ tmp ; BN-fold     (shuffle-split dots)
//   Phase 3: out[b,c,n] = x[b,c,n] + zbn[c]                (coalesced f4 RMW)
// Softmax over singleton axis == 1  =>  attention collapses to spatial sum.
// Wq, Wk are mathematically dead.
// ---------------------------------------------------------------------------
__global__ void __launch_bounds__(THREADS, 2)
k_fused(const float* __restrict__ x,
        const float* __restrict__ y,
        const float* __restrict__ Wv,
        const float* __restrict__ Wz,
        const float* __restrict__ bn_w,
        const float* __restrict__ bn_b,
        const float* __restrict__ bn_m,
        const float* __restrict__ bn_v,
        float* __restrict__ out) {
    __shared__ float ys[Cc];
    __shared__ float tmp[CH];
    __shared__ float zbn[Cc];

    const int b    = blockIdx.x;
    const int t    = threadIdx.x;
    const int warp = t >> 5;          // 0..15
    const int lane = t & 31;

    const size_t slab = (size_t)b * (Cc * NN);   // floats
    const float4* yb = reinterpret_cast<const float4*>(y + slab);

    // ---------------- Phase 1: spatial sum of y per channel ----------------
    // 16 warps x 16 channels each. Row = 49 float4 (coalesced: lanes 0..31
    // read 512B contiguous; lanes 0..16 read the 17-f4 tail).
    #pragma unroll 4
    for (int k = 0; k < 16; k++) {
        const int ch = warp * 16 + k;
        const float4* row = yb + ch * ROW_F4;
        float4 v = row[lane];
        float s = v.x + v.y + v.z + v.w;
        if (lane < N4 - 32) {
            float4 w2 = row[lane + 32];
            s += w2.x + w2.y + w2.z + w2.w;
        }
        #pragma unroll
        for (int o = 16; o; o >>= 1) s += __shfl_xor_sync(0xFFFFFFFFu, s, o);
        if (lane == 0) ys[ch] = s;
    }
    __syncthreads();

    // ---------------- Phase 2a: tmp[ch] = Wv[ch,:] . ys  (4 threads/ch) ----
    {
        const int ch = t >> 2, part = t & 3;       // 128 ch x 4 parts
        const float4* wr = reinterpret_cast<const float4*>(Wv + ch * Cc) + part * 16;
        const float* yss = ys + part * 64;
        float acc = 0.0f;
        #pragma unroll
        for (int i = 0; i < 16; i++) {
            float4 v = wr[i];
            acc += v.x * yss[4*i]   + v.y * yss[4*i+1]
                 + v.z * yss[4*i+2] + v.w * yss[4*i+3];
        }
        acc += __shfl_xor_sync(0xFFFFFFFFu, acc, 1);
        acc += __shfl_xor_sync(0xFFFFFFFFu, acc, 2);
        if (part == 0) tmp[ch] = acc;
    }
    __syncthreads();

    // ---------------- Phase 2b: z[o] = Wz[o,:] . tmp, BN  (2 threads/o) ----
    {
        const int o = t >> 1, part = t & 1;        // 256 o x 2 parts
        const float4* wr = reinterpret_cast<const float4*>(Wz + o * CH) + part * 16;
        const float* tp = tmp + part * 64;
        float acc = 0.0f;
        #pragma unroll
        for (int i = 0; i < 16; i++) {
            float4 v = wr[i];
            acc += v.x * tp[4*i]   + v.y * tp[4*i+1]
                 + v.z * tp[4*i+2] + v.w * tp[4*i+3];
        }
        acc += __shfl_xor_sync(0xFFFFFFFFu, acc, 1);
        if (part == 0) {
            const float inv = rsqrtf(bn_v[o] + EPS);
            zbn[o] = (acc - bn_m[o]) * inv * bn_w[o] + bn_b[o];
        }
    }
    __syncthreads();

    // ---------------- Phase 3: out = x + zbn[ch]  (coalesced float4) -------
    const float4* xb = reinterpret_cast<const float4*>(x + slab);
    float4*       ob = reinterpret_cast<float4*>(out) + (size_t)b * BATCH_F4;
    #pragma unroll 4
    for (int i = t; i < BATCH_F4; i += THREADS) {
        const int ch = i / N4;                     // IMAD magic-number div
        const float z = zbn[ch];
        float4 v = xb[i];
        v.x += z; v.y += z; v.z += z; v.w += z;
        ob[i] = v;
    }
}

// ---------------------------------------------------------------------------
// Inputs (metadata order):
//  0:x 1:y 2:Wq 3:Wk 4:Wv 5:Wz 6:bn_weight 7:bn_bias 8:bn_mean 9:bn_var
// ---------------------------------------------------------------------------
extern "C" void kernel_launch(void* const* d_in, const int* in_sizes, int n_in,
                              void* d_out, int out_size) {
    const float* x    = (const float*)d_in[0];
    const float* y    = (const float*)d_in[1];
    const float* Wv   = (const float*)d_in[4];
    const float* Wz   = (const float*)d_in[5];
    const float* bn_w = (const float*)d_in[6];
    const float* bn_b = (const float*)d_in[7];
    const float* bn_m = (const float*)d_in[8];
    const float* bn_v = (const float*)d_in[9];
    float* out = (float*)d_out;

    k_fused<<<Bb, THREADS>>>(x, y, Wv, Wz, bn_w, bn_b, bn_m, bn_v, out);
}